// round 3
// baseline (speedup 1.0000x reference)
#include <cuda_runtime.h>
#include <math.h>
#include <stdint.h>

#define N_SEQ 2048
#define D_MODEL 1024
#define NH 16
#define DH 64

// Scratch (allocation-free rules: device globals)
__device__ float g_q[N_SEQ * D_MODEL];
__device__ float g_k[N_SEQ * D_MODEL];
__device__ float g_v[N_SEQ * D_MODEL];
__device__ float g_attn[N_SEQ * D_MODEL];

// ---------------------------------------------------------------------------
// GEMM: C[2048,1024] = A[2048,1024] @ B[1024,1024] + bias[1024]
// BM=128, BN=64, BK=16, 256 threads, 8x4 per-thread microtile
// ---------------------------------------------------------------------------
__global__ __launch_bounds__(256) void gemm_bias_kernel(
    const float* __restrict__ A, const float* __restrict__ B,
    const float* __restrict__ bias, float* __restrict__ C)
{
    __shared__ float As[16][132];
    __shared__ float Bs[16][68];
    const int t  = threadIdx.x;
    const int tr = t >> 4, tc = t & 15;
    const int m0 = blockIdx.y * 128, n0 = blockIdx.x * 64;

    float acc[8][4];
#pragma unroll
    for (int i = 0; i < 8; i++)
#pragma unroll
        for (int j = 0; j < 4; j++) acc[i][j] = 0.f;

    for (int k0 = 0; k0 < 1024; k0 += 16) {
#pragma unroll
        for (int i = 0; i < 2; i++) {
            int e = t + i * 256;                 // 0..511
            int row = e >> 2, kv = (e & 3) << 2; // 128 rows x 4 float4
            float4 v = *reinterpret_cast<const float4*>(
                A + (size_t)(m0 + row) * 1024 + k0 + kv);
            As[kv + 0][row] = v.x; As[kv + 1][row] = v.y;
            As[kv + 2][row] = v.z; As[kv + 3][row] = v.w;
        }
        {
            int row = t >> 4, nv = (t & 15) << 2;
            float4 v = *reinterpret_cast<const float4*>(
                B + (size_t)(k0 + row) * 1024 + n0 + nv);
            Bs[row][nv + 0] = v.x; Bs[row][nv + 1] = v.y;
            Bs[row][nv + 2] = v.z; Bs[row][nv + 3] = v.w;
        }
        __syncthreads();
#pragma unroll
        for (int kk = 0; kk < 16; kk++) {
            float a[8], b[4];
#pragma unroll
            for (int i = 0; i < 8; i++) a[i] = As[kk][tr * 8 + i];
#pragma unroll
            for (int j = 0; j < 4; j++) b[j] = Bs[kk][tc * 4 + j];
#pragma unroll
            for (int i = 0; i < 8; i++)
#pragma unroll
                for (int j = 0; j < 4; j++)
                    acc[i][j] = fmaf(a[i], b[j], acc[i][j]);
        }
        __syncthreads();
    }
#pragma unroll
    for (int i = 0; i < 8; i++) {
        int m = m0 + tr * 8 + i;
#pragma unroll
        for (int j = 0; j < 4; j++) {
            int n = n0 + tc * 4 + j;
            C[(size_t)m * 1024 + n] = acc[i][j] + bias[n];
        }
    }
}

// ---------------------------------------------------------------------------
// RoPE: reference applies apply_rope to the FLAT (N, 1024) tensor with
// rot = freqs.shape[-1] = 64, so ONLY columns 0..63 are rotated; the other
// 960 columns pass through. Interleaved pairs; freqs[n][2i]==freqs[n][2i+1].
// One thread per (row, pair): 2048 rows x 32 pairs.
// ---------------------------------------------------------------------------
__global__ __launch_bounds__(256) void rope_kernel(
    float* __restrict__ q, float* __restrict__ k, const float* __restrict__ freqs)
{
    const int g = blockIdx.x * blockDim.x + threadIdx.x;   // 0 .. 2048*32-1
    const int n = g >> 5;
    const int p = g & 31;          // pair 0..31 within first 64 cols
    const int col = p * 2;
    float f = freqs[n * DH + col]; // even index of the repeated pair
    float s, c;
    sincosf(f, &s, &c);
    size_t idx = (size_t)n * D_MODEL + col;
    float q0 = q[idx], q1 = q[idx + 1];
    q[idx]     = q0 * c - q1 * s;
    q[idx + 1] = q1 * c + q0 * s;
    float k0 = k[idx], k1 = k[idx + 1];
    k[idx]     = k0 * c - k1 * s;
    k[idx + 1] = k1 * c + k0 * s;
}

// ---------------------------------------------------------------------------
// Flash-style attention with dual online softmax (full + window +/-128).
// Block = (query tile of 64, head). 256 threads.
// ---------------------------------------------------------------------------
__global__ __launch_bounds__(256) void attn_kernel(
    const float* __restrict__ Q, const float* __restrict__ K,
    const float* __restrict__ V,
    float* __restrict__ attn_out, float* __restrict__ resid_out)
{
    extern __shared__ float sm[];
    float* Qs = sm;               // 64 x 65
    float* Ks = Qs + 64 * 65;
    float* Vs = Ks + 64 * 65;
    float* Ss = Vs + 64 * 65;
    float* Ps = Ss + 64 * 65;

    const int t    = threadIdx.x;
    const int qt   = blockIdx.x;          // 0..31
    const int h    = blockIdx.y;          // 0..15
    const int q0   = qt * 64;
    const int hoff = h * DH;

    // Q tile load (once)
#pragma unroll
    for (int i = 0; i < 4; i++) {
        int e = t + i * 256;
        int row = e >> 4, cv = (e & 15) << 2;
        float4 v = *reinterpret_cast<const float4*>(
            Q + (size_t)(q0 + row) * D_MODEL + hoff + cv);
        Qs[row * 65 + cv + 0] = v.x; Qs[row * 65 + cv + 1] = v.y;
        Qs[row * 65 + cv + 2] = v.z; Qs[row * 65 + cv + 3] = v.w;
    }

    const int tr = t >> 4, tc = t & 15;    // S-compute map (4x4 microtile)
    const int rp = t >> 3;                 // row pair id 0..31
    const int oc = t & 7;                  // octet lane
    const int r0 = rp * 2, r1 = rp * 2 + 1;
    const int d0 = oc * 8;
    const int qi0 = q0 + r0, qi1 = q0 + r1;

    float accf0[8], accf1[8], accw0[8], accw1[8];
#pragma unroll
    for (int i = 0; i < 8; i++) { accf0[i] = accf1[i] = accw0[i] = accw1[i] = 0.f; }
    float mf0 = -1e30f, mf1 = -1e30f, lf0 = 0.f, lf1 = 0.f;
    float mw0 = -1e30f, mw1 = -1e30f, lw0 = 0.f, lw1 = 0.f;

    for (int kt = 0; kt < 32; kt++) {
        const int k0 = kt * 64;
        __syncthreads();   // protect Ks/Vs/Ps/Ss from previous iteration readers
#pragma unroll
        for (int i = 0; i < 4; i++) {
            int e = t + i * 256;
            int row = e >> 4, cv = (e & 15) << 2;
            float4 kv = *reinterpret_cast<const float4*>(
                K + (size_t)(k0 + row) * D_MODEL + hoff + cv);
            Ks[row * 65 + cv + 0] = kv.x; Ks[row * 65 + cv + 1] = kv.y;
            Ks[row * 65 + cv + 2] = kv.z; Ks[row * 65 + cv + 3] = kv.w;
            float4 vv = *reinterpret_cast<const float4*>(
                V + (size_t)(k0 + row) * D_MODEL + hoff + cv);
            Vs[row * 65 + cv + 0] = vv.x; Vs[row * 65 + cv + 1] = vv.y;
            Vs[row * 65 + cv + 2] = vv.z; Vs[row * 65 + cv + 3] = vv.w;
        }
        __syncthreads();

        // S = scale * Q @ K^T  (64x64 tile, 4x4 per thread)
        {
            float s4[4][4];
#pragma unroll
            for (int i = 0; i < 4; i++)
#pragma unroll
                for (int j = 0; j < 4; j++) s4[i][j] = 0.f;
#pragma unroll 8
            for (int kk = 0; kk < 64; kk++) {
                float a[4], b[4];
#pragma unroll
                for (int i = 0; i < 4; i++) a[i] = Qs[(tr * 4 + i) * 65 + kk];
#pragma unroll
                for (int j = 0; j < 4; j++) b[j] = Ks[(tc * 4 + j) * 65 + kk];
#pragma unroll
                for (int i = 0; i < 4; i++)
#pragma unroll
                    for (int j = 0; j < 4; j++)
                        s4[i][j] = fmaf(a[i], b[j], s4[i][j]);
            }
#pragma unroll
            for (int i = 0; i < 4; i++)
#pragma unroll
                for (int j = 0; j < 4; j++)
                    Ss[(tr * 4 + i) * 65 + tc * 4 + j] = s4[i][j] * 0.125f;
        }
        __syncthreads();

        // ---- full softmax (online) ----
        float tm0 = -1e30f, tm1 = -1e30f;
#pragma unroll
        for (int c = 0; c < 8; c++) {
            tm0 = fmaxf(tm0, Ss[r0 * 65 + d0 + c]);
            tm1 = fmaxf(tm1, Ss[r1 * 65 + d0 + c]);
        }
#pragma unroll
        for (int w = 1; w < 8; w <<= 1) {
            tm0 = fmaxf(tm0, __shfl_xor_sync(0xffffffffu, tm0, w, 8));
            tm1 = fmaxf(tm1, __shfl_xor_sync(0xffffffffu, tm1, w, 8));
        }
        float mn0 = fmaxf(mf0, tm0), mn1 = fmaxf(mf1, tm1);
        float cr0 = __expf(mf0 - mn0), cr1 = __expf(mf1 - mn1);
        float ps0 = 0.f, ps1 = 0.f;
#pragma unroll
        for (int c = 0; c < 8; c++) {
            float p0 = __expf(Ss[r0 * 65 + d0 + c] - mn0);
            float p1 = __expf(Ss[r1 * 65 + d0 + c] - mn1);
            Ps[r0 * 65 + d0 + c] = p0;
            Ps[r1 * 65 + d0 + c] = p1;
            ps0 += p0; ps1 += p1;
        }
#pragma unroll
        for (int w = 1; w < 8; w <<= 1) {
            ps0 += __shfl_xor_sync(0xffffffffu, ps0, w, 8);
            ps1 += __shfl_xor_sync(0xffffffffu, ps1, w, 8);
        }
        lf0 = lf0 * cr0 + ps0;  lf1 = lf1 * cr1 + ps1;
        mf0 = mn0;  mf1 = mn1;
#pragma unroll
        for (int i = 0; i < 8; i++) { accf0[i] *= cr0; accf1[i] *= cr1; }
        __syncwarp();
        // PV (full)
#pragma unroll 4
        for (int c = 0; c < 64; c++) {
            float p0 = Ps[r0 * 65 + c], p1 = Ps[r1 * 65 + c];
#pragma unroll
            for (int i = 0; i < 8; i++) {
                float v = Vs[c * 65 + d0 + i];
                accf0[i] = fmaf(p0, v, accf0[i]);
                accf1[i] = fmaf(p1, v, accf1[i]);
            }
        }

        // ---- windowed softmax: only key tiles intersecting the +/-128 band
        if (kt >= qt - 2 && kt <= qt + 2) {
            __syncwarp();  // PV-full done reading Ps before overwrite
            float tw0 = -1e30f, tw1 = -1e30f;
#pragma unroll
            for (int c = 0; c < 8; c++) {
                int j = k0 + d0 + c;
                float s0v = Ss[r0 * 65 + d0 + c];
                float s1v = Ss[r1 * 65 + d0 + c];
                if (j >= qi0 - 128 && j <= qi0 + 128) tw0 = fmaxf(tw0, s0v);
                if (j >= qi1 - 128 && j <= qi1 + 128) tw1 = fmaxf(tw1, s1v);
            }
#pragma unroll
            for (int w = 1; w < 8; w <<= 1) {
                tw0 = fmaxf(tw0, __shfl_xor_sync(0xffffffffu, tw0, w, 8));
                tw1 = fmaxf(tw1, __shfl_xor_sync(0xffffffffu, tw1, w, 8));
            }
            float mn0w = fmaxf(mw0, tw0), mn1w = fmaxf(mw1, tw1);
            float cw0 = __expf(mw0 - mn0w), cw1 = __expf(mw1 - mn1w);
            float pw0 = 0.f, pw1 = 0.f;
#pragma unroll
            for (int c = 0; c < 8; c++) {
                int j = k0 + d0 + c;
                float p0 = (j >= qi0 - 128 && j <= qi0 + 128)
                               ? __expf(Ss[r0 * 65 + d0 + c] - mn0w) : 0.f;
                float p1 = (j >= qi1 - 128 && j <= qi1 + 128)
                               ? __expf(Ss[r1 * 65 + d0 + c] - mn1w) : 0.f;
                Ps[r0 * 65 + d0 + c] = p0;
                Ps[r1 * 65 + d0 + c] = p1;
                pw0 += p0; pw1 += p1;
            }
#pragma unroll
            for (int w = 1; w < 8; w <<= 1) {
                pw0 += __shfl_xor_sync(0xffffffffu, pw0, w, 8);
                pw1 += __shfl_xor_sync(0xffffffffu, pw1, w, 8);
            }
            lw0 = lw0 * cw0 + pw0;  lw1 = lw1 * cw1 + pw1;
            mw0 = mn0w;  mw1 = mn1w;
#pragma unroll
            for (int i = 0; i < 8; i++) { accw0[i] *= cw0; accw1[i] *= cw1; }
            __syncwarp();
#pragma unroll 4
            for (int c = 0; c < 64; c++) {
                float p0 = Ps[r0 * 65 + c], p1 = Ps[r1 * 65 + c];
#pragma unroll
                for (int i = 0; i < 8; i++) {
                    float v = Vs[c * 65 + d0 + i];
                    accw0[i] = fmaf(p0, v, accw0[i]);
                    accw1[i] = fmaf(p1, v, accw1[i]);
                }
            }
        }
    }

    const float if0 = 1.f / lf0, if1 = 1.f / lf1;
    const float iw0 = 1.f / lw0, iw1 = 1.f / lw1;
#pragma unroll
    for (int i = 0; i < 8; i++) {
        float o0 = accf0[i] * if0;
        float o1 = accf1[i] * if1;
        attn_out[(size_t)qi0 * D_MODEL + hoff + d0 + i] = o0;
        attn_out[(size_t)qi1 * D_MODEL + hoff + d0 + i] = o1;
        resid_out[((size_t)h * N_SEQ + qi0) * DH + d0 + i] = o0 - accw0[i] * iw0;
        resid_out[((size_t)h * N_SEQ + qi1) * DH + d0 + i] = o1 - accw1[i] * iw1;
    }
}

// ---------------------------------------------------------------------------
extern "C" void kernel_launch(void* const* d_in, const int* in_sizes, int n_in,
                              void* d_out, int out_size)
{
    const float* x     = (const float*)d_in[0];
    // d_in[1] = mask (all-True for this problem; masking is a no-op)
    const float* freqs = (const float*)d_in[2];
    const float* Wq    = (const float*)d_in[3];
    const float* bq    = (const float*)d_in[4];
    const float* Wk    = (const float*)d_in[5];
    const float* bk    = (const float*)d_in[6];
    const float* Wv    = (const float*)d_in[7];
    const float* bv    = (const float*)d_in[8];
    const float* Wo    = (const float*)d_in[9];
    const float* bo    = (const float*)d_in[10];
    float* out = (float*)d_out;

    float *qp, *kp, *vp, *ap;
    cudaGetSymbolAddress((void**)&qp, g_q);
    cudaGetSymbolAddress((void**)&kp, g_k);
    cudaGetSymbolAddress((void**)&vp, g_v);
    cudaGetSymbolAddress((void**)&ap, g_attn);

    const int SMEM_ATTN = 5 * 64 * 65 * (int)sizeof(float);  // 83200 B
    cudaFuncSetAttribute(attn_kernel,
                         cudaFuncAttributeMaxDynamicSharedMemorySize, SMEM_ATTN);

    dim3 gemm_grid(1024 / 64, 2048 / 128);   // (16,16)

    gemm_bias_kernel<<<gemm_grid, 256>>>(x, Wq, bq, qp);
    gemm_bias_kernel<<<gemm_grid, 256>>>(x, Wk, bk, kp);
    gemm_bias_kernel<<<gemm_grid, 256>>>(x, Wv, bv, vp);

    // RoPE only touches the first 64 columns (2048 rows x 32 pairs)
    rope_kernel<<<(N_SEQ * 32) / 256, 256>>>(qp, kp, freqs);

    float* resid = out + (size_t)N_SEQ * D_MODEL;
    attn_kernel<<<dim3(32, NH), 256, SMEM_ATTN>>>(qp, kp, vp, ap, resid);

    gemm_bias_kernel<<<gemm_grid, 256>>>(ap, Wo, bo, out);
}

// round 4
// speedup vs baseline: 3.0623x; 3.0623x over previous
#include <cuda_runtime.h>
#include <cuda_bf16.h>
#include <math.h>
#include <stdint.h>

#define N_SEQ 2048
#define D_MODEL 1024
#define NH 16
#define DH 64

// Scratch (allocation-free rules: device globals)
__device__ float g_q[N_SEQ * D_MODEL];
__device__ float g_k[N_SEQ * D_MODEL];
__device__ float g_v[N_SEQ * D_MODEL];
__device__ float g_attn[N_SEQ * D_MODEL];

// ---------------------------------------------------------------------------
// mma.sync bf16 helpers (hi/lo split emulation: 3 passes -> ~2^-16 accuracy)
// ---------------------------------------------------------------------------
__device__ __forceinline__ uint32_t smaddr(const void* p) {
    return (uint32_t)__cvta_generic_to_shared(p);
}
__device__ __forceinline__ void ldsm4(uint32_t r[4], uint32_t a) {
    asm volatile("ldmatrix.sync.aligned.m8n8.x4.shared.b16 {%0,%1,%2,%3}, [%4];"
                 : "=r"(r[0]), "=r"(r[1]), "=r"(r[2]), "=r"(r[3]) : "r"(a));
}
__device__ __forceinline__ void ldsm4t(uint32_t r[4], uint32_t a) {
    asm volatile("ldmatrix.sync.aligned.m8n8.x4.trans.shared.b16 {%0,%1,%2,%3}, [%4];"
                 : "=r"(r[0]), "=r"(r[1]), "=r"(r[2]), "=r"(r[3]) : "r"(a));
}
__device__ __forceinline__ void mma_bf16(float* d, const uint32_t* a, const uint32_t* b) {
    asm volatile(
        "mma.sync.aligned.m16n8k16.row.col.f32.bf16.bf16.f32 "
        "{%0,%1,%2,%3}, {%4,%5,%6,%7}, {%8,%9}, {%0,%1,%2,%3};"
        : "+f"(d[0]), "+f"(d[1]), "+f"(d[2]), "+f"(d[3])
        : "r"(a[0]), "r"(a[1]), "r"(a[2]), "r"(a[3]), "r"(b[0]), "r"(b[1]));
}
__device__ __forceinline__ void mma3(float* d, const uint32_t* ah, const uint32_t* al,
                                     const uint32_t* bh, const uint32_t* bl) {
    mma_bf16(d, ah, bh);
    mma_bf16(d, ah, bl);
    mma_bf16(d, al, bh);
}
__device__ __forceinline__ uint32_t pack2(__nv_bfloat16 a, __nv_bfloat16 b) {
    __nv_bfloat162 t;
    t.x = a; t.y = b;
    return *reinterpret_cast<uint32_t*>(&t);
}
// split (a,b) into packed hi / packed lo bf16x2
__device__ __forceinline__ void split2(float a, float b, uint32_t& hi, uint32_t& lo) {
    __nv_bfloat16 ah = __float2bfloat16(a), bh = __float2bfloat16(b);
    __nv_bfloat16 al = __float2bfloat16(a - __bfloat162float(ah));
    __nv_bfloat16 bl = __float2bfloat16(b - __bfloat162float(bh));
    hi = pack2(ah, bh);
    lo = pack2(al, bl);
}
// fragment address helpers (stride in bf16 elements)
__device__ __forceinline__ uint32_t addrA(uint32_t base, int stride, int m0, int k0, int lane) {
    int r = m0 + (lane & 15);
    int c = k0 + ((lane >> 4) << 3);
    return base + (uint32_t)(r * stride + c) * 2u;
}
__device__ __forceinline__ uint32_t addrBnk(uint32_t base, int stride, int n0, int k0, int lane) {
    int r = n0 + (lane & 7) + ((lane >> 4) << 3);
    int c = k0 + (((lane >> 3) & 1) << 3);
    return base + (uint32_t)(r * stride + c) * 2u;
}
__device__ __forceinline__ uint32_t addrBt(uint32_t base, int stride, int k0, int n0, int lane) {
    int r = k0 + (lane & 15);
    int c = n0 + ((lane >> 4) << 3);
    return base + (uint32_t)(r * stride + c) * 2u;
}

// ---------------------------------------------------------------------------
// GEMM: C[2048,1024] = A[2048,1024] @ W[1024,1024] + bias (bf16-split HMMA)
// Block 128x128, 8 warps (2m x 4n), warp tile 64x32, BK=32.
// A smem [m][k] stride 40; W smem [k][n] stride 136 (B-frags via ldsm.trans).
// ---------------------------------------------------------------------------
__global__ __launch_bounds__(256) void gemm_mma(
    const float* __restrict__ A, const float* __restrict__ Wt,
    const float* __restrict__ bias, float* __restrict__ C)
{
    __shared__ __nv_bfloat16 Ahi[128 * 40], Alo[128 * 40];
    __shared__ __nv_bfloat16 Bhi[32 * 136], Blo[32 * 136];
    const int t = threadIdx.x, lane = t & 31, w = t >> 5;
    const int wm = w >> 2, wn = w & 3;
    const int m0 = blockIdx.y * 128, n0 = blockIdx.x * 128;
    const uint32_t aHi = smaddr(Ahi), aLo = smaddr(Alo);
    const uint32_t bHi = smaddr(Bhi), bLo = smaddr(Blo);

    float acc[4][4][4];
#pragma unroll
    for (int i = 0; i < 4; i++)
#pragma unroll
        for (int j = 0; j < 4; j++)
#pragma unroll
            for (int f = 0; f < 4; f++) acc[i][j][f] = 0.f;

    for (int k0 = 0; k0 < 1024; k0 += 32) {
        __syncthreads();
#pragma unroll
        for (int i = 0; i < 4; i++) {      // A 128x32
            int e = t + i * 256;
            int row = e >> 3, kv = (e & 7) << 2;
            float4 v = *reinterpret_cast<const float4*>(
                A + (size_t)(m0 + row) * 1024 + k0 + kv);
            uint32_t h0, l0, h1, l1;
            split2(v.x, v.y, h0, l0); split2(v.z, v.w, h1, l1);
            *reinterpret_cast<uint32_t*>(Ahi + row * 40 + kv)     = h0;
            *reinterpret_cast<uint32_t*>(Ahi + row * 40 + kv + 2) = h1;
            *reinterpret_cast<uint32_t*>(Alo + row * 40 + kv)     = l0;
            *reinterpret_cast<uint32_t*>(Alo + row * 40 + kv + 2) = l1;
        }
#pragma unroll
        for (int i = 0; i < 4; i++) {      // W 32x128 (natural)
            int e = t + i * 256;
            int kr = e >> 5, nv = (e & 31) << 2;
            float4 v = *reinterpret_cast<const float4*>(
                Wt + (size_t)(k0 + kr) * 1024 + n0 + nv);
            uint32_t h0, l0, h1, l1;
            split2(v.x, v.y, h0, l0); split2(v.z, v.w, h1, l1);
            *reinterpret_cast<uint32_t*>(Bhi + kr * 136 + nv)     = h0;
            *reinterpret_cast<uint32_t*>(Bhi + kr * 136 + nv + 2) = h1;
            *reinterpret_cast<uint32_t*>(Blo + kr * 136 + nv)     = l0;
            *reinterpret_cast<uint32_t*>(Blo + kr * 136 + nv + 2) = l1;
        }
        __syncthreads();
#pragma unroll
        for (int ks = 0; ks < 32; ks += 16) {
            uint32_t ah[4][4], al[4][4];
#pragma unroll
            for (int mb = 0; mb < 4; mb++) {
                ldsm4(ah[mb], addrA(aHi, 40, wm * 64 + mb * 16, ks, lane));
                ldsm4(al[mb], addrA(aLo, 40, wm * 64 + mb * 16, ks, lane));
            }
#pragma unroll
            for (int g = 0; g < 2; g++) {
                uint32_t bh[4], bl[4];
                ldsm4t(bh, addrBt(bHi, 136, ks, wn * 32 + g * 16, lane));
                ldsm4t(bl, addrBt(bLo, 136, ks, wn * 32 + g * 16, lane));
#pragma unroll
                for (int mb = 0; mb < 4; mb++) {
                    mma3(acc[mb][g * 2],     ah[mb], al[mb], bh,     bl);
                    mma3(acc[mb][g * 2 + 1], ah[mb], al[mb], bh + 2, bl + 2);
                }
            }
        }
    }
#pragma unroll
    for (int mb = 0; mb < 4; mb++) {
        int rlo = m0 + wm * 64 + mb * 16 + (lane >> 2);
        int rhi = rlo + 8;
#pragma unroll
        for (int nb = 0; nb < 4; nb++) {
            int col = n0 + wn * 32 + nb * 8 + (lane & 3) * 2;
            float b0 = bias[col], b1 = bias[col + 1];
            *reinterpret_cast<float2*>(C + (size_t)rlo * 1024 + col) =
                make_float2(acc[mb][nb][0] + b0, acc[mb][nb][1] + b1);
            *reinterpret_cast<float2*>(C + (size_t)rhi * 1024 + col) =
                make_float2(acc[mb][nb][2] + b0, acc[mb][nb][3] + b1);
        }
    }
}

// ---------------------------------------------------------------------------
// RoPE: only columns 0..63 of the flat (N,1024) tensor are rotated.
// ---------------------------------------------------------------------------
__global__ __launch_bounds__(256) void rope_kernel(
    float* __restrict__ q, float* __restrict__ k, const float* __restrict__ freqs)
{
    const int g = blockIdx.x * blockDim.x + threadIdx.x;   // 0 .. 2048*32-1
    const int n = g >> 5;
    const int p = g & 31;
    const int col = p * 2;
    float f = freqs[n * DH + col];
    float s, c;
    sincosf(f, &s, &c);
    size_t idx = (size_t)n * D_MODEL + col;
    float q0 = q[idx], q1 = q[idx + 1];
    q[idx]     = q0 * c - q1 * s;
    q[idx + 1] = q1 * c + q0 * s;
    float k0 = k[idx], k1 = k[idx + 1];
    k[idx]     = k0 * c - k1 * s;
    k[idx + 1] = k1 * c + k0 * s;
}

// ---------------------------------------------------------------------------
// Attention: flash-style dual online softmax, HMMA for S and PV.
// Block = (64-query tile, head). 8 warps arranged 4m x 2n (warp tile 16x32).
// smem layout (bytes):
//   Qhi 0      Qlo 9216   Khi 18432  Klo 27648  Vhi 36864  Vlo 46080
//   Ss  55296 (f32 64x68) Phi 72704  Plo 81920  stats 91136..92672
// ---------------------------------------------------------------------------
#define SM_QHI 0
#define SM_QLO 9216
#define SM_KHI 18432
#define SM_KLO 27648
#define SM_VHI 36864
#define SM_VLO 46080
#define SM_SS  55296
#define SM_PHI 72704
#define SM_PLO 81920
#define SM_ST  91136
#define SMEM_ATTN 92672

__global__ __launch_bounds__(256, 2) void attn_mma(
    const float* __restrict__ Q, const float* __restrict__ K,
    const float* __restrict__ V,
    float* __restrict__ attn_out, float* __restrict__ resid_out)
{
    extern __shared__ char sm[];
    __nv_bfloat16* Qhi = (__nv_bfloat16*)(sm + SM_QHI);
    __nv_bfloat16* Qlo = (__nv_bfloat16*)(sm + SM_QLO);
    __nv_bfloat16* Khi = (__nv_bfloat16*)(sm + SM_KHI);
    __nv_bfloat16* Klo = (__nv_bfloat16*)(sm + SM_KLO);
    __nv_bfloat16* Vhi = (__nv_bfloat16*)(sm + SM_VHI);
    __nv_bfloat16* Vlo = (__nv_bfloat16*)(sm + SM_VLO);
    float* Ss  = (float*)(sm + SM_SS);
    __nv_bfloat16* Phi = (__nv_bfloat16*)(sm + SM_PHI);
    __nv_bfloat16* Plo = (__nv_bfloat16*)(sm + SM_PLO);
    float* m_f  = (float*)(sm + SM_ST);
    float* l_f  = m_f + 64;
    float* cr_f = m_f + 128;
    float* m_w  = m_f + 192;
    float* l_w  = m_f + 256;
    float* cr_w = m_f + 320;

    const uint32_t qHi = smaddr(Qhi), qLo = smaddr(Qlo);
    const uint32_t kHi = smaddr(Khi), kLo = smaddr(Klo);
    const uint32_t vHi = smaddr(Vhi), vLo = smaddr(Vlo);
    const uint32_t pHi = smaddr(Phi), pLo = smaddr(Plo);

    const int t = threadIdx.x, lane = t & 31, w = t >> 5;
    const int wm = w >> 1, wn = w & 1;
    const int qt = blockIdx.x, h = blockIdx.y;
    const int q0 = qt * 64, hoff = h * DH;

    if (t < 64) { m_f[t] = -1e30f; l_f[t] = 0.f; m_w[t] = -1e30f; l_w[t] = 0.f; }

    // Q tile load + split (64x64)
#pragma unroll
    for (int i = 0; i < 4; i++) {
        int e = t + i * 256;
        int row = e >> 4, cv = (e & 15) << 2;
        float4 v = *reinterpret_cast<const float4*>(
            Q + (size_t)(q0 + row) * D_MODEL + hoff + cv);
        uint32_t h0, l0, h1, l1;
        split2(v.x, v.y, h0, l0); split2(v.z, v.w, h1, l1);
        *reinterpret_cast<uint32_t*>(Qhi + row * 72 + cv)     = h0;
        *reinterpret_cast<uint32_t*>(Qhi + row * 72 + cv + 2) = h1;
        *reinterpret_cast<uint32_t*>(Qlo + row * 72 + cv)     = l0;
        *reinterpret_cast<uint32_t*>(Qlo + row * 72 + cv + 2) = l1;
    }

    const int rp = t >> 3, oc = t & 7;
    const int r0 = rp * 2, r1 = r0 + 1, d0 = oc * 8;
    const int qi0 = q0 + r0, qi1 = q0 + r1;
    const int srlo = wm * 16 + (lane >> 2), srhi = srlo + 8;

    float accf[4][4], accw[4][4];
#pragma unroll
    for (int i = 0; i < 4; i++)
#pragma unroll
        for (int j = 0; j < 4; j++) { accf[i][j] = 0.f; accw[i][j] = 0.f; }

    for (int kt = 0; kt < 32; kt++) {
        const int k0 = kt * 64;
        __syncthreads();
        // K, V tile load + split
#pragma unroll
        for (int i = 0; i < 4; i++) {
            int e = t + i * 256;
            int row = e >> 4, cv = (e & 15) << 2;
            float4 kv = *reinterpret_cast<const float4*>(
                K + (size_t)(k0 + row) * D_MODEL + hoff + cv);
            uint32_t h0, l0, h1, l1;
            split2(kv.x, kv.y, h0, l0); split2(kv.z, kv.w, h1, l1);
            *reinterpret_cast<uint32_t*>(Khi + row * 72 + cv)     = h0;
            *reinterpret_cast<uint32_t*>(Khi + row * 72 + cv + 2) = h1;
            *reinterpret_cast<uint32_t*>(Klo + row * 72 + cv)     = l0;
            *reinterpret_cast<uint32_t*>(Klo + row * 72 + cv + 2) = l1;
            float4 vv = *reinterpret_cast<const float4*>(
                V + (size_t)(k0 + row) * D_MODEL + hoff + cv);
            split2(vv.x, vv.y, h0, l0); split2(vv.z, vv.w, h1, l1);
            *reinterpret_cast<uint32_t*>(Vhi + row * 72 + cv)     = h0;
            *reinterpret_cast<uint32_t*>(Vhi + row * 72 + cv + 2) = h1;
            *reinterpret_cast<uint32_t*>(Vlo + row * 72 + cv)     = l0;
            *reinterpret_cast<uint32_t*>(Vlo + row * 72 + cv + 2) = l1;
        }
        __syncthreads();

        // ---- S = Q @ K^T (warp tile 16x32) ----
        {
            float sacc[4][4];
#pragma unroll
            for (int i = 0; i < 4; i++)
#pragma unroll
                for (int j = 0; j < 4; j++) sacc[i][j] = 0.f;
#pragma unroll
            for (int ks = 0; ks < 64; ks += 16) {
                uint32_t ah[4], al[4];
                ldsm4(ah, addrA(qHi, 72, wm * 16, ks, lane));
                ldsm4(al, addrA(qLo, 72, wm * 16, ks, lane));
#pragma unroll
                for (int g = 0; g < 2; g++) {
                    uint32_t bh[4], bl[4];
                    ldsm4(bh, addrBnk(kHi, 72, wn * 32 + g * 16, ks, lane));
                    ldsm4(bl, addrBnk(kLo, 72, wn * 32 + g * 16, ks, lane));
                    mma3(sacc[g * 2],     ah, al, bh,     bl);
                    mma3(sacc[g * 2 + 1], ah, al, bh + 2, bl + 2);
                }
            }
#pragma unroll
            for (int nb = 0; nb < 4; nb++) {
                int col = wn * 32 + nb * 8 + (lane & 3) * 2;
                *reinterpret_cast<float2*>(&Ss[srlo * 68 + col]) =
                    make_float2(sacc[nb][0] * 0.125f, sacc[nb][1] * 0.125f);
                *reinterpret_cast<float2*>(&Ss[srhi * 68 + col]) =
                    make_float2(sacc[nb][2] * 0.125f, sacc[nb][3] * 0.125f);
            }
        }
        __syncthreads();

        // ---- full online softmax (fp32) -> Phi/Plo + row stats ----
        {
            float mo0 = m_f[r0], mo1 = m_f[r1];
            float s0v[8], s1v[8];
            float tm0 = -1e30f, tm1 = -1e30f;
#pragma unroll
            for (int c = 0; c < 8; c++) {
                s0v[c] = Ss[r0 * 68 + d0 + c];
                s1v[c] = Ss[r1 * 68 + d0 + c];
                tm0 = fmaxf(tm0, s0v[c]); tm1 = fmaxf(tm1, s1v[c]);
            }
#pragma unroll
            for (int sw = 1; sw < 8; sw <<= 1) {
                tm0 = fmaxf(tm0, __shfl_xor_sync(0xffffffffu, tm0, sw, 8));
                tm1 = fmaxf(tm1, __shfl_xor_sync(0xffffffffu, tm1, sw, 8));
            }
            float mn0 = fmaxf(mo0, tm0), mn1 = fmaxf(mo1, tm1);
            float ps0 = 0.f, ps1 = 0.f;
            float p0[8], p1[8];
#pragma unroll
            for (int c = 0; c < 8; c++) {
                p0[c] = __expf(s0v[c] - mn0); ps0 += p0[c];
                p1[c] = __expf(s1v[c] - mn1); ps1 += p1[c];
            }
#pragma unroll
            for (int cp = 0; cp < 4; cp++) {
                uint32_t hi, lo;
                split2(p0[2 * cp], p0[2 * cp + 1], hi, lo);
                *reinterpret_cast<uint32_t*>(Phi + r0 * 72 + d0 + 2 * cp) = hi;
                *reinterpret_cast<uint32_t*>(Plo + r0 * 72 + d0 + 2 * cp) = lo;
                split2(p1[2 * cp], p1[2 * cp + 1], hi, lo);
                *reinterpret_cast<uint32_t*>(Phi + r1 * 72 + d0 + 2 * cp) = hi;
                *reinterpret_cast<uint32_t*>(Plo + r1 * 72 + d0 + 2 * cp) = lo;
            }
#pragma unroll
            for (int sw = 1; sw < 8; sw <<= 1) {
                ps0 += __shfl_xor_sync(0xffffffffu, ps0, sw, 8);
                ps1 += __shfl_xor_sync(0xffffffffu, ps1, sw, 8);
            }
            if (oc == 0) {
                float cr0 = __expf(mo0 - mn0), cr1 = __expf(mo1 - mn1);
                l_f[r0] = l_f[r0] * cr0 + ps0;  m_f[r0] = mn0;  cr_f[r0] = cr0;
                l_f[r1] = l_f[r1] * cr1 + ps1;  m_f[r1] = mn1;  cr_f[r1] = cr1;
            }
        }
        __syncthreads();

        // ---- PV (full) ----
        {
            float clo = cr_f[srlo], chi = cr_f[srhi];
#pragma unroll
            for (int nb = 0; nb < 4; nb++) {
                accf[nb][0] *= clo; accf[nb][1] *= clo;
                accf[nb][2] *= chi; accf[nb][3] *= chi;
            }
#pragma unroll
            for (int ks = 0; ks < 64; ks += 16) {
                uint32_t ah[4], al[4];
                ldsm4(ah, addrA(pHi, 72, wm * 16, ks, lane));
                ldsm4(al, addrA(pLo, 72, wm * 16, ks, lane));
#pragma unroll
                for (int g = 0; g < 2; g++) {
                    uint32_t bh[4], bl[4];
                    ldsm4t(bh, addrBt(vHi, 72, ks, wn * 32 + g * 16, lane));
                    ldsm4t(bl, addrBt(vLo, 72, ks, wn * 32 + g * 16, lane));
                    mma3(accf[g * 2],     ah, al, bh,     bl);
                    mma3(accf[g * 2 + 1], ah, al, bh + 2, bl + 2);
                }
            }
        }

        // ---- window path ----
        if (kt >= qt - 2 && kt <= qt + 2) {
            __syncthreads();   // PV-full done with Phi/Plo
            {
                float mo0 = m_w[r0], mo1 = m_w[r1];
                float tw0 = -1e30f, tw1 = -1e30f;
                float s0v[8], s1v[8];
#pragma unroll
                for (int c = 0; c < 8; c++) {
                    s0v[c] = Ss[r0 * 68 + d0 + c];
                    s1v[c] = Ss[r1 * 68 + d0 + c];
                    int j = k0 + d0 + c;
                    if (j >= qi0 - 128 && j <= qi0 + 128) tw0 = fmaxf(tw0, s0v[c]);
                    if (j >= qi1 - 128 && j <= qi1 + 128) tw1 = fmaxf(tw1, s1v[c]);
                }
#pragma unroll
                for (int sw = 1; sw < 8; sw <<= 1) {
                    tw0 = fmaxf(tw0, __shfl_xor_sync(0xffffffffu, tw0, sw, 8));
                    tw1 = fmaxf(tw1, __shfl_xor_sync(0xffffffffu, tw1, sw, 8));
                }
                float mn0 = fmaxf(mo0, tw0), mn1 = fmaxf(mo1, tw1);
                float ps0 = 0.f, ps1 = 0.f;
                float p0[8], p1[8];
#pragma unroll
                for (int c = 0; c < 8; c++) {
                    int j = k0 + d0 + c;
                    p0[c] = (j >= qi0 - 128 && j <= qi0 + 128) ? __expf(s0v[c] - mn0) : 0.f;
                    p1[c] = (j >= qi1 - 128 && j <= qi1 + 128) ? __expf(s1v[c] - mn1) : 0.f;
                    ps0 += p0[c]; ps1 += p1[c];
                }
#pragma unroll
                for (int cp = 0; cp < 4; cp++) {
                    uint32_t hi, lo;
                    split2(p0[2 * cp], p0[2 * cp + 1], hi, lo);
                    *reinterpret_cast<uint32_t*>(Phi + r0 * 72 + d0 + 2 * cp) = hi;
                    *reinterpret_cast<uint32_t*>(Plo + r0 * 72 + d0 + 2 * cp) = lo;
                    split2(p1[2 * cp], p1[2 * cp + 1], hi, lo);
                    *reinterpret_cast<uint32_t*>(Phi + r1 * 72 + d0 + 2 * cp) = hi;
                    *reinterpret_cast<uint32_t*>(Plo + r1 * 72 + d0 + 2 * cp) = lo;
                }
#pragma unroll
                for (int sw = 1; sw < 8; sw <<= 1) {
                    ps0 += __shfl_xor_sync(0xffffffffu, ps0, sw, 8);
                    ps1 += __shfl_xor_sync(0xffffffffu, ps1, sw, 8);
                }
                if (oc == 0) {
                    float cr0 = __expf(mo0 - mn0), cr1 = __expf(mo1 - mn1);
                    l_w[r0] = l_w[r0] * cr0 + ps0;  m_w[r0] = mn0;  cr_w[r0] = cr0;
                    l_w[r1] = l_w[r1] * cr1 + ps1;  m_w[r1] = mn1;  cr_w[r1] = cr1;
                }
            }
            __syncthreads();
            {
                float clo = cr_w[srlo], chi = cr_w[srhi];
#pragma unroll
                for (int nb = 0; nb < 4; nb++) {
                    accw[nb][0] *= clo; accw[nb][1] *= clo;
                    accw[nb][2] *= chi; accw[nb][3] *= chi;
                }
#pragma unroll
                for (int ks = 0; ks < 64; ks += 16) {
                    uint32_t ah[4], al[4];
                    ldsm4(ah, addrA(pHi, 72, wm * 16, ks, lane));
                    ldsm4(al, addrA(pLo, 72, wm * 16, ks, lane));
#pragma unroll
                    for (int g = 0; g < 2; g++) {
                        uint32_t bh[4], bl[4];
                        ldsm4t(bh, addrBt(vHi, 72, ks, wn * 32 + g * 16, lane));
                        ldsm4t(bl, addrBt(vLo, 72, ks, wn * 32 + g * 16, lane));
                        mma3(accw[g * 2],     ah, al, bh,     bl);
                        mma3(accw[g * 2 + 1], ah, al, bh + 2, bl + 2);
                    }
                }
            }
        }
    }
    __syncthreads();

    // epilogue
    {
        float ilf0 = 1.f / l_f[srlo], ilf1 = 1.f / l_f[srhi];
        float ilw0 = 1.f / l_w[srlo], ilw1 = 1.f / l_w[srhi];
#pragma unroll
        for (int nb = 0; nb < 4; nb++) {
            int col = wn * 32 + nb * 8 + (lane & 3) * 2;
            float o0 = accf[nb][0] * ilf0, o1 = accf[nb][1] * ilf0;
            float o2 = accf[nb][2] * ilf1, o3 = accf[nb][3] * ilf1;
            *reinterpret_cast<float2*>(
                attn_out + (size_t)(q0 + srlo) * D_MODEL + hoff + col) = make_float2(o0, o1);
            *reinterpret_cast<float2*>(
                attn_out + (size_t)(q0 + srhi) * D_MODEL + hoff + col) = make_float2(o2, o3);
            *reinterpret_cast<float2*>(
                resid_out + ((size_t)h * N_SEQ + q0 + srlo) * DH + col) =
                make_float2(o0 - accw[nb][0] * ilw0, o1 - accw[nb][1] * ilw0);
            *reinterpret_cast<float2*>(
                resid_out + ((size_t)h * N_SEQ + q0 + srhi) * DH + col) =
                make_float2(o2 - accw[nb][2] * ilw1, o3 - accw[nb][3] * ilw1);
        }
    }
}

// ---------------------------------------------------------------------------
extern "C" void kernel_launch(void* const* d_in, const int* in_sizes, int n_in,
                              void* d_out, int out_size)
{
    const float* x     = (const float*)d_in[0];
    // d_in[1] = mask (all-True; no-op)
    const float* freqs = (const float*)d_in[2];
    const float* Wq    = (const float*)d_in[3];
    const float* bq    = (const float*)d_in[4];
    const float* Wk    = (const float*)d_in[5];
    const float* bk    = (const float*)d_in[6];
    const float* Wv    = (const float*)d_in[7];
    const float* bv    = (const float*)d_in[8];
    const float* Wo    = (const float*)d_in[9];
    const float* bo    = (const float*)d_in[10];
    float* out = (float*)d_out;

    float *qp, *kp, *vp, *ap;
    cudaGetSymbolAddress((void**)&qp, g_q);
    cudaGetSymbolAddress((void**)&kp, g_k);
    cudaGetSymbolAddress((void**)&vp, g_v);
    cudaGetSymbolAddress((void**)&ap, g_attn);

    cudaFuncSetAttribute(attn_mma,
                         cudaFuncAttributeMaxDynamicSharedMemorySize, SMEM_ATTN);

    dim3 gemm_grid(D_MODEL / 128, N_SEQ / 128);   // (8,16)

    gemm_mma<<<gemm_grid, 256>>>(x, Wq, bq, qp);
    gemm_mma<<<gemm_grid, 256>>>(x, Wk, bk, kp);
    gemm_mma<<<gemm_grid, 256>>>(x, Wv, bv, vp);

    rope_kernel<<<(N_SEQ * 32) / 256, 256>>>(qp, kp, freqs);

    float* resid = out + (size_t)N_SEQ * D_MODEL;
    attn_mma<<<dim3(32, NH), 256, SMEM_ATTN>>>(qp, kp, vp, ap, resid);

    gemm_mma<<<gemm_grid, 256>>>(ap, Wo, bo, out);
}